// round 1
// baseline (speedup 1.0000x reference)
#include <cuda_runtime.h>

// CFConv: y[i] = sum over edges e with idx_i[e]==i of x[idx_j[e]] * Wij[e]
// x: [N=50000, F=64] f32, Wij: [E=1.25M, F=64] f32, idx sorted by idx_i.
//
// Strategy: warp-per-chunk segmented reduction exploiting sorted idx_i.
//   - Each warp owns CHUNK contiguous edges; lane l owns features [2l, 2l+1] (float2).
//   - Accumulate in registers while idx_i unchanged; on change, flush.
//   - Interior segments (start AND end inside the chunk) are exclusively owned
//     by this warp (sorted indices) -> plain coalesced store.
//   - First and last segments of each chunk may span chunk boundaries -> atomicAdd.
//   - Output zero-initialized first (harness poisons d_out with 0xAA).

#define CHUNK 128
#define FEAT  64

__global__ void zero_kernel(float4* __restrict__ y4, int n4) {
    int i = blockIdx.x * blockDim.x + threadIdx.x;
    if (i < n4) y4[i] = make_float4(0.f, 0.f, 0.f, 0.f);
}

template <typename IdxT>
__device__ __forceinline__ void cfconv_loop(
    const float2* __restrict__ x2, const float2* __restrict__ W2,
    const IdxT* __restrict__ idx_i, const IdxT* __restrict__ idx_j,
    float* __restrict__ y, long long e, long long eEnd, int lane)
{
    long long prev = (long long)idx_i[e];
    bool first = true;  // first segment may extend into the previous chunk
    float2 acc = make_float2(0.f, 0.f);

    #pragma unroll 4
    for (; e < eEnd; ++e) {
        long long ii = (long long)idx_i[e];
        long long jj = (long long)idx_j[e];
        if (ii != prev) {
            float* dst = y + prev * FEAT + lane * 2;
            if (first) {
                atomicAdd(dst,     acc.x);
                atomicAdd(dst + 1, acc.y);
                first = false;
            } else {
                // interior segment: exclusively owned (idx_i sorted) -> plain store
                *reinterpret_cast<float2*>(dst) = acc;
            }
            acc = make_float2(0.f, 0.f);
            prev = ii;
        }
        float2 w  = W2[e * (FEAT / 2) + lane];
        float2 xv = x2[jj * (FEAT / 2) + lane];
        acc.x = fmaf(xv.x, w.x, acc.x);
        acc.y = fmaf(xv.y, w.y, acc.y);
    }
    // last segment may extend into the next chunk -> atomic
    float* dst = y + prev * FEAT + lane * 2;
    atomicAdd(dst,     acc.x);
    atomicAdd(dst + 1, acc.y);
}

__global__ __launch_bounds__(256) void cfconv_kernel(
    const float2* __restrict__ x2, const float2* __restrict__ W2,
    const void* __restrict__ idx_i_p, const void* __restrict__ idx_j_p,
    float* __restrict__ y, int E)
{
    int gwarp = (blockIdx.x * blockDim.x + threadIdx.x) >> 5;
    int lane  = threadIdx.x & 31;

    long long e = (long long)gwarp * CHUNK;
    if (e >= E) return;
    long long eEnd = e + CHUNK;
    if (eEnd > E) eEnd = E;

    // Runtime dtype probe: idx arrays are int64 (per reference) OR int32 (JAX
    // x64-disabled downcast). For LE int64 data, the int32 word at odd element
    // (E/2)|1 is a high word == 0 (all indices < 2^31). For int32 data, the
    // sorted idx_i median is ~N/2 != 0. Reading only the first E int32 words
    // is in-bounds for either dtype. Uniform branch across the grid.
    int probe = reinterpret_cast<const int*>(idx_i_p)[(E / 2) | 1];
    if (probe == 0) {
        cfconv_loop<long long>(x2, W2,
                               reinterpret_cast<const long long*>(idx_i_p),
                               reinterpret_cast<const long long*>(idx_j_p),
                               y, e, eEnd, lane);
    } else {
        cfconv_loop<int>(x2, W2,
                         reinterpret_cast<const int*>(idx_i_p),
                         reinterpret_cast<const int*>(idx_j_p),
                         y, e, eEnd, lane);
    }
}

extern "C" void kernel_launch(void* const* d_in, const int* in_sizes, int n_in,
                              void* d_out, int out_size)
{
    const float* x   = (const float*)d_in[0];   // [N, 64]
    const float* Wij = (const float*)d_in[1];   // [E, 64]
    const void*  ii  = d_in[2];                 // [E] int64 or int32
    const void*  jj  = d_in[3];                 // [E] int64 or int32
    float*       y   = (float*)d_out;           // [N, 64]

    int E = in_sizes[1] / FEAT;                 // dtype-independent edge count

    // 1) zero the output (poisoned to 0xAA by the harness)
    int n4 = out_size / 4;
    zero_kernel<<<(n4 + 255) / 256, 256>>>((float4*)y, n4);

    // 2) segmented gather-multiply-scatter
    int nwarps  = (E + CHUNK - 1) / CHUNK;
    int nblocks = (nwarps + 7) / 8;             // 8 warps per 256-thread block
    cfconv_kernel<<<nblocks, 256>>>((const float2*)x, (const float2*)Wij,
                                    ii, jj, y, E);
}